// round 1
// baseline (speedup 1.0000x reference)
#include <cuda_runtime.h>
#include <math.h>

#define STEPF 0.1f
#define MAXL_G 4096
#define MAXL_S 2048
#define MAXNS 64
#define DELAY_N 30

__device__ float g_aif[MAXL_G];
__device__ int   g_idx[MAXNS];
__device__ int   g_L;

// ---------------------------------------------------------------------------
// Prep: build fine-grid AIF (interp + 3s delay) and searchsorted sample indices
// ---------------------------------------------------------------------------
__global__ void dce_prep_kernel(const float* __restrict__ sample_time,
                                const float* __restrict__ Cp, int ns)
{
    // L = round(t_end / STEP) + 1, as the reference computes in float64
    double t_end = (double)sample_time[ns - 1];
    int L = (int)llrint(t_end / 0.1) + 1;
    if (L > MAXL_S) L = MAXL_S;
    if (threadIdx.x == 0) g_L = L;

    // aif[i] = 0 for i < DELAY, else interp(t = (i-DELAY)*0.1f, sample_time, Cp)
    for (int i = threadIdx.x; i < L; i += blockDim.x) {
        float val = 0.f;
        if (i >= DELAY_N) {
            int src = i - DELAY_N;
            float t = (float)src * STEPF;
            if (t <= sample_time[0]) {
                val = Cp[0];
            } else if (t >= sample_time[ns - 1]) {
                val = Cp[ns - 1];
            } else {
                // largest k with sample_time[k] <= t
                int lo = 0, hi = ns - 1;
                while (lo + 1 < hi) {
                    int mid = (lo + hi) >> 1;
                    if (sample_time[mid] <= t) lo = mid; else hi = mid;
                }
                float x0 = sample_time[lo], x1 = sample_time[lo + 1];
                val = Cp[lo] + (t - x0) * (Cp[lo + 1] - Cp[lo]) / (x1 - x0);
            }
        }
        g_aif[i] = val;
    }

    // idx[j] = searchsorted(t_samp, sample_time[j], 'left'), clamped like JAX gather
    int jmax = ns < MAXNS ? ns : MAXNS;
    for (int j = threadIdx.x; j < jmax; j += blockDim.x) {
        float st = sample_time[j];
        int lo = 0, hi = L;
        while (lo < hi) {
            int mid = (lo + hi) >> 1;
            // t_samp[mid] = f32(mid) * f32(0.1): identical IEEE ops to jnp
            if ((float)mid * STEPF < st) lo = mid + 1; else hi = mid;
        }
        g_idx[j] = lo < (L - 1) ? lo : (L - 1);
    }
}

// ---------------------------------------------------------------------------
// Main: per-pixel bi-exponential recurrence convolution + SPGR signal
// ---------------------------------------------------------------------------
__global__ void __launch_bounds__(256)
dce_main_kernel(const float* __restrict__ param,
                float* __restrict__ out, int npix, int ns)
{
    __shared__ float s_aif[MAXL_S];
    __shared__ int   s_idx[MAXNS];

    const int L = g_L;
    for (int i = threadIdx.x; i < L; i += blockDim.x) s_aif[i] = g_aif[i];
    int jmax = ns < MAXNS ? ns : MAXNS;
    for (int j = threadIdx.x; j < jmax; j += blockDim.x) s_idx[j] = g_idx[j];
    __syncthreads();

    int pix = blockIdx.x * blockDim.x + threadIdx.x;
    if (pix >= npix) return;

    const float ve  = param[pix];
    const float vp  = param[npix + pix];
    const float fpp = param[2 * npix + pix];
    const float ps  = param[3 * npix + pix];

    const float Te = ve / ps;
    const float T  = (vp + ve) / fpp;
    const float Tc = vp / fpp;
    const float s  = T + Te;
    const float disc = sqrtf(fmaxf(s * s - 4.f * Tc * Te, 0.f));
    const float inv2 = 1.f / (2.f * Tc * Te);
    const float thp = (s + disc) * inv2;
    const float thm = (s - disc) * inv2;

    const float rm = expf(-thm * STEPF);
    const float rp = expf(-thp * STEPF);

    // Geometric-series normalization sums via expm1f (accurate for small theta*dt)
    const float Lf   = (float)L;
    const float SEm  = (-expm1f(-thm * STEPF * Lf)) / (-expm1f(-thm * STEPF));
    const float SEp  = (-expm1f(-thp * STEPF * Lf)) / (-expm1f(-thp * STEPF));

    const float cm  = 1.f - Te * thm;    // hp coefficient on the theta_m stream
    const float cpp = Te * thp - 1.f;    // hp coefficient on the theta_p stream
    // prefactor A = thp*thm/(thp-thm) cancels between h and its normalization
    const float inv_she = 1.f / (SEm - SEp);
    const float inv_shp = 1.f / fmaf(cm, SEm, cpp * SEp);

    // SPGR signal constants (M_steady == SIG_BASELINE analytically; keep the
    // f32 roundoff structure of the reference anyway)
    const float cosfa = 0.98480775301220806f;   // cos(10 deg)
    const float E1    = expf(-0.00487f);        // exp(-TR*R1)
    const float M0t   = 100.f * (1.f - cosfa * E1) / (1.f - E1);
    const float base  = 100.f - M0t * (1.f - E1) / (1.f - E1 * cosfa);

    float Sm = 0.f, Sp = 0.f;
    int m = 0;
    for (int j = 0; j < ns; ++j) {
        const int target = s_idx[j];
        #pragma unroll 4
        for (; m <= target; ++m) {
            const float a = s_aif[m];
            Sm = fmaf(Sm, rm, a);
            Sp = fmaf(Sp, rp, a);
        }
        const float ce   = inv_she * (Sm - Sp);
        const float cpv  = inv_shp * fmaf(cm, Sm, cpp * Sp);
        const float conc = vp * cpv + ve * ce;
        // E1CA = exp(-TR*(R1 + R1CA*conc))
        const float E1CA = expf(-0.00487f * fmaf(4.3f, conc, 1.0f));
        const float sig  = M0t * (1.f - E1CA) / (1.f - E1CA * cosfa) + base;
        out[(size_t)j * npix + pix] = sig;
    }
}

extern "C" void kernel_launch(void* const* d_in, const int* in_sizes, int n_in,
                              void* d_out, int out_size)
{
    const float* param       = (const float*)d_in[0];
    const float* sample_time = (const float*)d_in[1];
    const float* Cp          = (const float*)d_in[2];
    float* out = (float*)d_out;

    const int ns   = in_sizes[1];
    const int npix = in_sizes[0] / 4;

    dce_prep_kernel<<<1, 256>>>(sample_time, Cp, ns);

    const int threads = 256;
    const int blocks  = (npix + threads - 1) / threads;
    dce_main_kernel<<<blocks, threads>>>(param, out, npix, ns);
}